// round 3
// baseline (speedup 1.0000x reference)
#include <cuda_runtime.h>
#include <cuda_bf16.h>
#include <math.h>

// ---------------------------------------------------------------------------
// ann2_snn1 — bit-faithful emulation of the JAX/XLA-CPU reference.
//
// Matching rules derived from XLA-CPU lowering:
//  * matmuls (Eigen gebp): per output element, ONE f32 accumulator, strictly
//    ascending k, fused FMA. -> all dots here are sequential __fmaf_rn chains.
//  * bias adds / relu / sigmoid: separate f32-rounded elementwise ops.
//  * logistic -> 0.5 + 0.5*tanh(0.5x), XLA rational tanh (mul/add poly, f32 div).
//  * scan body ops: psp = ((a1*p1) + (a2*p2)) + drive, each op f32-rounded;
//    v  = ((sigma*v) * (1-s)) + cur, each op f32-rounded; s = (v >= 1).
//  * constants = double expressions rounded once to f32.
// ---------------------------------------------------------------------------

#define BATCH 1024
#define HID   500
#define NIN   784
#define NOUT  10
#define TLEN  100

__device__ float g_h[BATCH * HID];
__device__ float g_drive[BATCH * HID];

// f32-rounded constants (from exact doubles)
#define A1F ((float)1.1466802242428472)    // exp(-1/4)+exp(-1)
#define A2F ((float)-0.28650479686019009)  // -exp(-1/4)*exp(-1)
#define SGF ((float)0.77880078307140487)   // exp(-1/4)

// XLA f32 tanh: clamp to +-7.90531110763549805, rational poly (separate
// mul/add rounds), pass-through for |x| < 0.0004.
__device__ __forceinline__ float xla_tanh_f32(float x)
{
    const float kMax = 7.90531110763549805f;
    float xc = fminf(fmaxf(x, -kMax), kMax);
    float x2 = __fmul_rn(xc, xc);
    float p = -2.76076847742355e-16f;
    p = __fadd_rn(__fmul_rn(p, x2), 2.00018790482477e-13f);
    p = __fadd_rn(__fmul_rn(p, x2), -8.60467152213735e-11f);
    p = __fadd_rn(__fmul_rn(p, x2), 5.12229709037114e-08f);
    p = __fadd_rn(__fmul_rn(p, x2), 1.48572235717979e-05f);
    p = __fadd_rn(__fmul_rn(p, x2), 6.37261928875436e-04f);
    p = __fadd_rn(__fmul_rn(p, x2), 4.89352455891786e-03f);
    float num = __fmul_rn(xc, p);
    float q = 1.19825839466702e-06f;
    q = __fadd_rn(__fmul_rn(q, x2), 1.18534705686654e-04f);
    q = __fadd_rn(__fmul_rn(q, x2), 2.26843463243900e-03f);
    q = __fadd_rn(__fmul_rn(q, x2), 4.89352518554385e-03f);
    float r = __fdiv_rn(num, q);
    return (fabsf(x) < 0.0004f) ? x : r;
}

__device__ __forceinline__ float xla_sigmoid(float x)
{
    float t = xla_tanh_f32(__fmul_rn(0.5f, x));
    return __fadd_rn(0.5f, __fmul_rn(0.5f, t));
}

// ---------------------------------------------------------------------------
// Tiled SGEMM: C[M,N] = act(A[M,K] @ W[N,K]^T + bias[N])
// BM=BN=64, BK=16, 256 threads, 4x4 register tile.
// Strictly ascending-k single-f32-accumulator FMA chain per output element
// (k-tail padded with zeros: fma(a,0,acc)==acc exactly, order preserved).
// ---------------------------------------------------------------------------
template<int ACT>
__global__ __launch_bounds__(256)
void gemm_bias_act(const float* __restrict__ A, const float* __restrict__ W,
                   const float* __restrict__ bias, float* __restrict__ C,
                   int M, int N, int K)
{
    __shared__ float As[16][64];
    __shared__ float Ws[16][64];

    const int tid  = threadIdx.x;
    const int tx   = tid & 15;
    const int ty   = tid >> 4;
    const int bm   = blockIdx.y * 64;
    const int bn   = blockIdx.x * 64;
    const int lrow = tid >> 2;
    const int lc4  = tid & 3;

    float acc[4][4] = {};

    for (int kb = 0; kb < K; kb += 16) {
        {
            int ak = kb + lc4 * 4;
            float4 av = make_float4(0.f, 0.f, 0.f, 0.f);
            const float* ap = A + (size_t)(bm + lrow) * K + ak;
            if (ak + 3 < K) {
                av = *(const float4*)ap;
            } else {
                float t0 = (ak + 0 < K) ? ap[0] : 0.f;
                float t1 = (ak + 1 < K) ? ap[1] : 0.f;
                float t2 = (ak + 2 < K) ? ap[2] : 0.f;
                float t3 = (ak + 3 < K) ? ap[3] : 0.f;
                av = make_float4(t0, t1, t2, t3);
            }
            As[lc4 * 4 + 0][lrow] = av.x;
            As[lc4 * 4 + 1][lrow] = av.y;
            As[lc4 * 4 + 2][lrow] = av.z;
            As[lc4 * 4 + 3][lrow] = av.w;
        }
        {
            int wr = bn + lrow;
            int wk = kb + lc4 * 4;
            float4 wv = make_float4(0.f, 0.f, 0.f, 0.f);
            if (wr < N) {
                const float* wp = W + (size_t)wr * K + wk;
                if (wk + 3 < K) {
                    wv = *(const float4*)wp;
                } else {
                    float t0 = (wk + 0 < K) ? wp[0] : 0.f;
                    float t1 = (wk + 1 < K) ? wp[1] : 0.f;
                    float t2 = (wk + 2 < K) ? wp[2] : 0.f;
                    float t3 = (wk + 3 < K) ? wp[3] : 0.f;
                    wv = make_float4(t0, t1, t2, t3);
                }
            }
            Ws[lc4 * 4 + 0][lrow] = wv.x;
            Ws[lc4 * 4 + 1][lrow] = wv.y;
            Ws[lc4 * 4 + 2][lrow] = wv.z;
            Ws[lc4 * 4 + 3][lrow] = wv.w;
        }
        __syncthreads();

        #pragma unroll
        for (int k = 0; k < 16; k++) {
            float4 a4 = *(const float4*)&As[k][ty * 4];
            float4 w4 = *(const float4*)&Ws[k][tx * 4];
            float a[4] = {a4.x, a4.y, a4.z, a4.w};
            float w[4] = {w4.x, w4.y, w4.z, w4.w};
            #pragma unroll
            for (int i = 0; i < 4; i++)
                #pragma unroll
                for (int j = 0; j < 4; j++)
                    acc[i][j] = __fmaf_rn(a[i], w[j], acc[i][j]);
        }
        __syncthreads();
    }

    #pragma unroll
    for (int j = 0; j < 4; j++) {
        int n = bn + tx * 4 + j;
        if (n >= N) continue;
        float bv = bias[n];
        #pragma unroll
        for (int i = 0; i < 4; i++) {
            int m = bm + ty * 4 + i;
            float x = __fadd_rn(acc[i][j], bv);
            if (ACT == 0) x = fmaxf(x, 0.f);
            else          x = xla_sigmoid(x);
            C[(size_t)m * N + n] = x;
        }
    }
}

// ---------------------------------------------------------------------------
// Scan kernel: one block per batch element b; faithful 100-step emulation.
//  phase 1: 500 threads iterate psp in f32 (exact reference op order),
//           staging psp[t][k] in shared.
//  phase 2: 500 threads = (t, j-pair); each computes 2 sequential-k f32 FMA
//           dot products cur0[t,j] = sum_k psp[t,k]*w3[j,k].
//  phase 3: 10 threads run the LIF recurrence with per-op f32 rounds.
// ---------------------------------------------------------------------------
__global__ __launch_bounds__(512)
void scan_kernel(const float* __restrict__ w3, const float* __restrict__ b3,
                 float* __restrict__ out)
{
    extern __shared__ float sm[];
    float* sp = sm;                    // [TLEN][HID]   psp
    float* sw = sm + TLEN * HID;       // [NOUT][HID]   w3
    float* sc = sw + NOUT * HID;       // [TLEN][NOUT]  dot results (pre-bias)

    const int b   = blockIdx.x;
    const int tid = threadIdx.x;

    for (int i = tid; i < NOUT * HID; i += 512) sw[i] = w3[i];

    // phase 1: psp iteration (no cross-thread deps; each thread owns one k)
    if (tid < HID) {
        float dr = g_drive[(size_t)b * HID + tid];
        float p1 = 0.f, p2 = 0.f;
        #pragma unroll 4
        for (int t = 0; t < TLEN; t++) {
            float ps = __fadd_rn(__fadd_rn(__fmul_rn(A1F, p1),
                                           __fmul_rn(A2F, p2)), dr);
            sp[t * HID + tid] = ps;
            p2 = p1; p1 = ps;
        }
    }
    __syncthreads();

    // phase 2: 1000 independent sequential-k dots, 2 per thread
    if (tid < 500) {
        const int tt = tid / 5;
        const int j0 = (tid % 5) * 2;
        const float* pr = sp + tt * HID;
        const float* w0 = sw + j0 * HID;
        const float* w1 = sw + (j0 + 1) * HID;
        float a0 = 0.f, a1 = 0.f;
        #pragma unroll 4
        for (int k = 0; k < HID; k += 4) {
            float4 pv  = *(const float4*)(pr + k);
            float4 wv0 = *(const float4*)(w0 + k);
            float4 wv1 = *(const float4*)(w1 + k);
            a0 = __fmaf_rn(pv.x, wv0.x, a0);
            a0 = __fmaf_rn(pv.y, wv0.y, a0);
            a0 = __fmaf_rn(pv.z, wv0.z, a0);
            a0 = __fmaf_rn(pv.w, wv0.w, a0);
            a1 = __fmaf_rn(pv.x, wv1.x, a1);
            a1 = __fmaf_rn(pv.y, wv1.y, a1);
            a1 = __fmaf_rn(pv.z, wv1.z, a1);
            a1 = __fmaf_rn(pv.w, wv1.w, a1);
        }
        sc[tt * NOUT + j0]     = a0;
        sc[tt * NOUT + j0 + 1] = a1;
    }
    __syncthreads();

    // phase 3: LIF recurrence, exact reference op order; stage spikes in sp
    if (tid < NOUT) {
        float bb = b3[tid];
        float v = 0.f, s = 0.f;
        for (int t = 0; t < TLEN; t++) {
            float cur = __fadd_rn(sc[t * NOUT + tid], bb);
            float t1  = __fmul_rn(SGF, v);
            float t2  = __fmul_rn(t1, __fsub_rn(1.f, s));
            float vn  = __fadd_rn(t2, cur);
            s = (vn >= 1.f) ? 1.f : 0.f;
            v = vn;
            sp[tid * TLEN + t] = s;   // sp region is free after phase 2
        }
    }
    __syncthreads();

    float* ob = out + (size_t)b * (NOUT * TLEN);
    for (int i = tid; i < NOUT * TLEN; i += 512) ob[i] = sp[i];
}

#define SCAN_SMEM ((TLEN * HID + NOUT * HID + TLEN * NOUT) * (int)sizeof(float))

extern "C" void kernel_launch(void* const* d_in, const int* in_sizes, int n_in,
                              void* d_out, int out_size)
{
    const float* inputs = (const float*)d_in[0];  // [1024, 784]
    const float* w1     = (const float*)d_in[1];  // [500, 784]
    const float* b1     = (const float*)d_in[2];  // [500]
    const float* w2     = (const float*)d_in[3];  // [500, 500]
    const float* b2     = (const float*)d_in[4];  // [500]
    const float* w3     = (const float*)d_in[5];  // [10, 500]
    const float* b3     = (const float*)d_in[6];  // [10]
    float* out          = (float*)d_out;          // [1024, 10, 100]

    float* h_buf;
    float* drive_buf;
    cudaGetSymbolAddress((void**)&h_buf, g_h);
    cudaGetSymbolAddress((void**)&drive_buf, g_drive);

    cudaFuncSetAttribute(scan_kernel,
                         cudaFuncAttributeMaxDynamicSharedMemorySize, SCAN_SMEM);

    dim3 blk(256);
    dim3 grd1((HID + 63) / 64, BATCH / 64);   // 8 x 16
    gemm_bias_act<0><<<grd1, blk>>>(inputs, w1, b1, h_buf, BATCH, HID, NIN);
    gemm_bias_act<1><<<grd1, blk>>>(h_buf, w2, b2, drive_buf, BATCH, HID, HID);
    scan_kernel<<<BATCH, 512, SCAN_SMEM>>>(w3, b3, out);
}

// round 4
// speedup vs baseline: 1.7014x; 1.7014x over previous
#include <cuda_runtime.h>
#include <cuda_bf16.h>
#include <math.h>

// ---------------------------------------------------------------------------
// ann2_snn1 — bit-faithful emulation of the JAX/XLA-CPU reference (verified
// rel_err == 0.0 in R3). Numerics contract (must not change):
//  * every dot product: ONE f32 accumulator, strictly ascending k, __fmaf_rn
//  * elementwise ops: separate f32 rounds in reference order
//  * logistic = 0.5 + 0.5*tanh(0.5x) with XLA's rational tanh
// Parallelization across outputs / t / batch is free.
// ---------------------------------------------------------------------------

#define BATCH 1024
#define HID   500
#define NIN   784
#define NOUT  10
#define TLEN  100

__device__ float g_h[BATCH * HID];
__device__ float g_drive[BATCH * HID];

#define A1F ((float)1.1466802242428472)    // exp(-1/4)+exp(-1)
#define A2F ((float)-0.28650479686019009)  // -exp(-1/4)*exp(-1)
#define SGF ((float)0.77880078307140487)   // exp(-1/4)

__device__ __forceinline__ float xla_tanh_f32(float x)
{
    const float kMax = 7.90531110763549805f;
    float xc = fminf(fmaxf(x, -kMax), kMax);
    float x2 = __fmul_rn(xc, xc);
    float p = -2.76076847742355e-16f;
    p = __fadd_rn(__fmul_rn(p, x2), 2.00018790482477e-13f);
    p = __fadd_rn(__fmul_rn(p, x2), -8.60467152213735e-11f);
    p = __fadd_rn(__fmul_rn(p, x2), 5.12229709037114e-08f);
    p = __fadd_rn(__fmul_rn(p, x2), 1.48572235717979e-05f);
    p = __fadd_rn(__fmul_rn(p, x2), 6.37261928875436e-04f);
    p = __fadd_rn(__fmul_rn(p, x2), 4.89352455891786e-03f);
    float num = __fmul_rn(xc, p);
    float q = 1.19825839466702e-06f;
    q = __fadd_rn(__fmul_rn(q, x2), 1.18534705686654e-04f);
    q = __fadd_rn(__fmul_rn(q, x2), 2.26843463243900e-03f);
    q = __fadd_rn(__fmul_rn(q, x2), 4.89352518554385e-03f);
    float r = __fdiv_rn(num, q);
    return (fabsf(x) < 0.0004f) ? x : r;
}

__device__ __forceinline__ float xla_sigmoid(float x)
{
    float t = xla_tanh_f32(__fmul_rn(0.5f, x));
    return __fadd_rn(0.5f, __fmul_rn(0.5f, t));
}

// ---------------------------------------------------------------------------
// Double-buffered SGEMM: C[M,N] = act(A[M,K] @ W[N,K]^T + bias[N])
// BM=64, BN=32, BK=16, 128 threads, 4x4 micro-tile, register-prefetch
// double buffering (one __syncthreads per k-tile).
// M is a multiple of 64. N,K guarded (zero-padded: exactness preserved since
// fma(0,0,acc)==acc).
// ---------------------------------------------------------------------------
#define BM 64
#define BN 32
#define BK 16
#define AS_LD 68
#define WS_LD 36

template<int ACT>
__global__ __launch_bounds__(128)
void gemm_bias_act(const float* __restrict__ A, const float* __restrict__ W,
                   const float* __restrict__ bias, float* __restrict__ C,
                   int M, int N, int K)
{
    __shared__ float As[2][BK][AS_LD];
    __shared__ float Ws[2][BK][WS_LD];

    const int tid = threadIdx.x;
    const int tx  = tid & 7;            // n dir: 8 x 4 = 32
    const int ty  = tid >> 3;           // m dir: 16 x 4 = 64
    const int bm  = blockIdx.y * BM;
    const int bn  = blockIdx.x * BN;

    // A loader: row lrow (0..63), two float4 at k = lc*8 + {0,4}
    const int lrow = tid >> 1;
    const int lc   = tid & 1;
    // W loader: row wrow (0..31), one float4 at k = wk4*4
    const int wrow = tid >> 2;
    const int wk4  = tid & 3;

    const int T = (K + BK - 1) / BK;

    float acc[4][4] = {};
    float4 pa0, pa1, pw;

    // ---- load helpers (guarded, zero-pad) ----
    auto loadA = [&](int kb, float4& r0, float4& r1) {
        const float* ap = A + (size_t)(bm + lrow) * K;
        int k0 = kb + lc * 8;
        #pragma unroll
        for (int f = 0; f < 2; f++) {
            int k = k0 + f * 4;
            float4 v;
            if (k + 3 < K) {
                v = *(const float4*)(ap + k);
            } else {
                v.x = (k + 0 < K) ? ap[k + 0] : 0.f;
                v.y = (k + 1 < K) ? ap[k + 1] : 0.f;
                v.z = (k + 2 < K) ? ap[k + 2] : 0.f;
                v.w = (k + 3 < K) ? ap[k + 3] : 0.f;
            }
            if (f == 0) r0 = v; else r1 = v;
        }
    };
    auto loadW = [&](int kb, float4& r) {
        int wr = bn + wrow;
        int k  = kb + wk4 * 4;
        float4 v = make_float4(0.f, 0.f, 0.f, 0.f);
        if (wr < N) {
            const float* wp = W + (size_t)wr * K;
            if (k + 3 < K) {
                v = *(const float4*)(wp + k);
            } else {
                v.x = (k + 0 < K) ? wp[k + 0] : 0.f;
                v.y = (k + 1 < K) ? wp[k + 1] : 0.f;
                v.z = (k + 2 < K) ? wp[k + 2] : 0.f;
                v.w = (k + 3 < K) ? wp[k + 3] : 0.f;
            }
        }
        r = v;
    };
    auto stage = [&](int buf, const float4& a0, const float4& a1, const float4& w) {
        int ka = lc * 8;
        As[buf][ka + 0][lrow] = a0.x;
        As[buf][ka + 1][lrow] = a0.y;
        As[buf][ka + 2][lrow] = a0.z;
        As[buf][ka + 3][lrow] = a0.w;
        As[buf][ka + 4][lrow] = a1.x;
        As[buf][ka + 5][lrow] = a1.y;
        As[buf][ka + 6][lrow] = a1.z;
        As[buf][ka + 7][lrow] = a1.w;
        int kw = wk4 * 4;
        Ws[buf][kw + 0][wrow] = w.x;
        Ws[buf][kw + 1][wrow] = w.y;
        Ws[buf][kw + 2][wrow] = w.z;
        Ws[buf][kw + 3][wrow] = w.w;
    };

    loadA(0, pa0, pa1);
    loadW(0, pw);
    stage(0, pa0, pa1, pw);
    __syncthreads();

    for (int it = 0; it < T; it++) {
        const int cur = it & 1;
        if (it + 1 < T) {
            loadA((it + 1) * BK, pa0, pa1);
            loadW((it + 1) * BK, pw);
        }
        #pragma unroll
        for (int k = 0; k < BK; k++) {
            float4 a4 = *(const float4*)&As[cur][k][ty * 4];
            float4 w4 = *(const float4*)&Ws[cur][k][tx * 4];
            float a[4] = {a4.x, a4.y, a4.z, a4.w};
            float w[4] = {w4.x, w4.y, w4.z, w4.w};
            #pragma unroll
            for (int i = 0; i < 4; i++)
                #pragma unroll
                for (int j = 0; j < 4; j++)
                    acc[i][j] = __fmaf_rn(a[i], w[j], acc[i][j]);
        }
        if (it + 1 < T) stage(cur ^ 1, pa0, pa1, pw);
        __syncthreads();
    }

    #pragma unroll
    for (int j = 0; j < 4; j++) {
        int n = bn + tx * 4 + j;
        if (n >= N) continue;
        float bv = bias[n];
        #pragma unroll
        for (int i = 0; i < 4; i++) {
            int m = bm + ty * 4 + i;
            float x = __fadd_rn(acc[i][j], bv);
            if (ACT == 0) x = fmaxf(x, 0.f);
            else          x = xla_sigmoid(x);
            C[(size_t)m * N + n] = x;
        }
    }
}

// ---------------------------------------------------------------------------
// Scan kernel: one block (256 threads) per batch element.
//  phase 1: 250 threads x 2 cols iterate psp (f32, exact reference op order),
//           staging sp[t][k] in shared (row stride 500, float4-aligned).
//  phase 2: 2 groups x 100 t threads; warp = fixed j-group, 32 t values ->
//           the 5 weight float4 loads per step are warp-broadcast (free),
//           psp float4 loads are phase-conflict-free (stride 500).
//           Each accumulator: strict ascending-k FMA chain.
//  phase 3: 10 threads run the LIF recurrence (per-op f32 rounds), staging
//           spikes into the (now free) sp region; coalesced copy out.
// ---------------------------------------------------------------------------
__global__ __launch_bounds__(256)
void scan_kernel(const float* __restrict__ w3, const float* __restrict__ b3,
                 float* __restrict__ out)
{
    extern __shared__ float sm[];
    float* sp = sm;                    // [TLEN][HID]  psp  (200,000 B)
    float* sw = sm + TLEN * HID;       // [NOUT][HID]  w3   ( 20,000 B)
    float* sc = sw + NOUT * HID;       // [TLEN][NOUT] dots (  4,000 B)

    const int b   = blockIdx.x;
    const int tid = threadIdx.x;

    // load w3 (coalesced float4)
    {
        const float4* src = (const float4*)w3;
        float4* dst = (float4*)sw;
        for (int i = tid; i < (NOUT * HID) / 4; i += 256) dst[i] = src[i];
    }

    // phase 1: psp recurrence, 2 columns per thread
    if (tid < 250) {
        const int k0 = tid, k1 = tid + 250;
        float d0 = g_drive[(size_t)b * HID + k0];
        float d1 = g_drive[(size_t)b * HID + k1];
        float p1a = 0.f, p2a = 0.f, p1b = 0.f, p2b = 0.f;
        #pragma unroll 4
        for (int t = 0; t < TLEN; t++) {
            float pa = __fadd_rn(__fadd_rn(__fmul_rn(A1F, p1a),
                                           __fmul_rn(A2F, p2a)), d0);
            float pb = __fadd_rn(__fadd_rn(__fmul_rn(A1F, p1b),
                                           __fmul_rn(A2F, p2b)), d1);
            sp[t * HID + k0] = pa;
            sp[t * HID + k1] = pb;
            p2a = p1a; p1a = pa;
            p2b = p1b; p1b = pb;
        }
    }
    __syncthreads();

    // phase 2: group g handles j = 5g..5g+4 for one t per thread
    {
        const int g = tid >> 7;          // 0..1
        const int t = tid & 127;         // <100 active
        if (t < TLEN) {
            const float* pr = sp + t * HID;
            const float* w0 = sw + (5 * g + 0) * HID;
            const float* w1 = sw + (5 * g + 1) * HID;
            const float* w2 = sw + (5 * g + 2) * HID;
            const float* w3r = sw + (5 * g + 3) * HID;
            const float* w4 = sw + (5 * g + 4) * HID;
            float a0 = 0.f, a1 = 0.f, a2 = 0.f, a3 = 0.f, a4 = 0.f;
            #pragma unroll 5
            for (int k = 0; k < HID; k += 4) {
                float4 pv = *(const float4*)(pr + k);
                float4 q0 = *(const float4*)(w0 + k);
                float4 q1 = *(const float4*)(w1 + k);
                float4 q2 = *(const float4*)(w2 + k);
                float4 q3 = *(const float4*)(w3r + k);
                float4 q4 = *(const float4*)(w4 + k);
                a0 = __fmaf_rn(pv.x, q0.x, a0); a0 = __fmaf_rn(pv.y, q0.y, a0);
                a0 = __fmaf_rn(pv.z, q0.z, a0); a0 = __fmaf_rn(pv.w, q0.w, a0);
                a1 = __fmaf_rn(pv.x, q1.x, a1); a1 = __fmaf_rn(pv.y, q1.y, a1);
                a1 = __fmaf_rn(pv.z, q1.z, a1); a1 = __fmaf_rn(pv.w, q1.w, a1);
                a2 = __fmaf_rn(pv.x, q2.x, a2); a2 = __fmaf_rn(pv.y, q2.y, a2);
                a2 = __fmaf_rn(pv.z, q2.z, a2); a2 = __fmaf_rn(pv.w, q2.w, a2);
                a3 = __fmaf_rn(pv.x, q3.x, a3); a3 = __fmaf_rn(pv.y, q3.y, a3);
                a3 = __fmaf_rn(pv.z, q3.z, a3); a3 = __fmaf_rn(pv.w, q3.w, a3);
                a4 = __fmaf_rn(pv.x, q4.x, a4); a4 = __fmaf_rn(pv.y, q4.y, a4);
                a4 = __fmaf_rn(pv.z, q4.z, a4); a4 = __fmaf_rn(pv.w, q4.w, a4);
            }
            float* scr = sc + t * NOUT + 5 * g;
            scr[0] = a0; scr[1] = a1; scr[2] = a2; scr[3] = a3; scr[4] = a4;
        }
    }
    __syncthreads();

    // phase 3: LIF recurrence (exact reference op order); spikes -> sp region
    if (tid < NOUT) {
        float bb = b3[tid];
        float v = 0.f, s = 0.f;
        float* spk = sp + tid * TLEN;
        for (int t = 0; t < TLEN; t++) {
            float cur = __fadd_rn(sc[t * NOUT + tid], bb);
            float t1  = __fmul_rn(SGF, v);
            float t2  = __fmul_rn(t1, __fsub_rn(1.f, s));
            float vn  = __fadd_rn(t2, cur);
            s = (vn >= 1.f) ? 1.f : 0.f;
            v = vn;
            spk[t] = s;
        }
    }
    __syncthreads();

    float* ob = out + (size_t)b * (NOUT * TLEN);
    for (int i = tid; i < NOUT * TLEN; i += 256) ob[i] = sp[i];
}

#define SCAN_SMEM ((TLEN * HID + NOUT * HID + TLEN * NOUT) * (int)sizeof(float))

extern "C" void kernel_launch(void* const* d_in, const int* in_sizes, int n_in,
                              void* d_out, int out_size)
{
    const float* inputs = (const float*)d_in[0];  // [1024, 784]
    const float* w1     = (const float*)d_in[1];  // [500, 784]
    const float* b1     = (const float*)d_in[2];  // [500]
    const float* w2     = (const float*)d_in[3];  // [500, 500]
    const float* b2     = (const float*)d_in[4];  // [500]
    const float* w3     = (const float*)d_in[5];  // [10, 500]
    const float* b3     = (const float*)d_in[6];  // [10]
    float* out          = (float*)d_out;          // [1024, 10, 100]

    float* h_buf;
    float* drive_buf;
    cudaGetSymbolAddress((void**)&h_buf, g_h);
    cudaGetSymbolAddress((void**)&drive_buf, g_drive);

    cudaFuncSetAttribute(scan_kernel,
                         cudaFuncAttributeMaxDynamicSharedMemorySize, SCAN_SMEM);

    dim3 blk(128);
    dim3 grd((HID + BN - 1) / BN, BATCH / BM);   // 16 x 16 = 256 blocks
    gemm_bias_act<0><<<grd, blk>>>(inputs, w1, b1, h_buf, BATCH, HID, NIN);
    gemm_bias_act<1><<<grd, blk>>>(h_buf, w2, b2, drive_buf, BATCH, HID, HID);
    scan_kernel<<<BATCH, 256, SCAN_SMEM>>>(w3, b3, out);
}